// round 15
// baseline (speedup 1.0000x reference)
#include <cuda_runtime.h>

#define N_FFT    800
#define HOP      200
#define BATCH    32
#define TLEN     480000
#define PAD      400
#define N_FRAMES 2401                 // frames per batch
#define NHOP     2404                 // hop blocks per batch: 480800/200
#define AOUT     58                   // C outputs (q positions) per A-tile
#define AHOPS    64                   // hop sums per A-tile incl. 3+3 halo
#define ATILES   42                   // ceil(NHOP / AOUT)
#define BBLK     37                   // consumer blocks per batch
#define RPB      (ATILES + BBLK)      // 79 blocks per batch group
#define NQUAD    (TLEN / 4)           // 120000 output quads per batch

#define PI_D 3.14159265358979323846

// Fully fused STFT->mag/phase->iSTFT (linear-collapse derivation, R3/R6):
//   Hann identities: win(r+400)=1-win(r), win(r+600)=1-win(r+200),
//   sum_j win(r+200j)^2 = 1.5 exactly.
//   Per hop block g: X=sum(x), A=sum(win(r)x), B=sum(win(r+200)x) (per parity).
//   S[f] = A[f] + B[f+1] + (X[f+2]-A[f+2]) + (X[f+3]-B[f+3]);  S=0 off-range.
//   out = 0.75*x + (C0 + win(r)*C1 + win(r+200)*C2)/800,
//     C0=S[q-2]+S[q-3], C1=S[q]-S[q-2], C2=S[q-1]-S[q-3]  (per parity).
//   Missing frame j at signal edge additionally: out -= 0.5*x*win(r+200j)^2.
//
// Single-launch producer/consumer: per batch, 42 A-blocks compute gC[b] and
// signal gDone[b]; 37 B-blocks (scheduled right after them in bid order)
// spin on gDone[b], then stream the synthesis. A-reads and B-writes of
// different batches overlap on DRAM instead of serializing across kernels.

__device__ float gC[BATCH][NHOP][8];   // {C0e,C0o,C1e,C1o,C2e,C2o,0,0}
__device__ unsigned int gDone[BATCH];

__global__ void reset_kernel() {
    if (threadIdx.x < BATCH) gDone[threadIdx.x] = 0u;
}

__global__ __launch_bounds__(256, 8)
void fused_kernel(const float* __restrict__ x, float* __restrict__ out) {
    __shared__ __align__(16) float sbuf[800];     // A: sw[400]+sXAB[64][6]=784; B: sw[800]

    const int bid = blockIdx.x;
    const int b   = bid / RPB;
    const int r   = bid - b * RPB;
    const int tid = threadIdx.x;

    if (r < ATILES) {
        // ---------------- producer (A): hop sums + C combos ----------------
        float* __restrict__ sw = sbuf;            // win[0..400)
        float (*sXAB)[6] = (float(*)[6])(sbuf + 400);
        const int Q0 = r * AOUT;
        const float* __restrict__ xb = x + (size_t)b * TLEN;

        for (int i = tid; i < 400; i += 256)
            sw[i] = 0.5f - 0.5f * __cosf((float)i * (float)(2.0 * PI_D / N_FFT));
        __syncthreads();

        const int grp = tid >> 2;                 // 0..63
        const int j   = tid & 3;
        const int gh  = Q0 - 3 + grp;             // hop index (may be off-range)
        const float4* __restrict__ sw4 = (const float4*)sw;

        float xe = 0.f, xo = 0.f, ae = 0.f, ao = 0.f, be = 0.f, bo = 0.f;
        if (gh >= 2 && gh <= 2401) {
            const float4* __restrict__ xs = (const float4*)xb + (50 * gh - 100);
            #pragma unroll
            for (int k = 0; k < 13; k++) {
                const int c = j + 4 * k;
                if (c < 50) {
                    const float4 v  = __ldg(&xs[c]);
                    const float4 wa = sw4[c];
                    const float4 wb = sw4[c + 50];
                    xe += v.x + v.z;                   xo += v.y + v.w;
                    ae = fmaf(wa.x, v.x, fmaf(wa.z, v.z, ae));
                    ao = fmaf(wa.y, v.y, fmaf(wa.w, v.w, ao));
                    be = fmaf(wb.x, v.x, fmaf(wb.z, v.z, be));
                    bo = fmaf(wb.y, v.y, fmaf(wb.w, v.w, bo));
                }
            }
        } else {
            #pragma unroll
            for (int k = 0; k < 13; k++) {
                const int c = j + 4 * k;
                if (c < 50) {
                    const int rr = 4 * c;
                    #pragma unroll
                    for (int e = 0; e < 4; e += 2) {
                        int p0 = 200 * gh + rr + e - PAD;
                        int p1 = p0 + 1;
                        p0 = p0 < 0 ? 0 : (p0 >= TLEN ? TLEN - 1 : p0);
                        p1 = p1 < 0 ? 0 : (p1 >= TLEN ? TLEN - 1 : p1);
                        const float v0 = xb[p0], v1 = xb[p1];
                        xe += v0;                          xo += v1;
                        ae = fmaf(sw[rr + e], v0, ae);     ao = fmaf(sw[rr + e + 1], v1, ao);
                        be = fmaf(sw[rr + e + 200], v0, be);
                        bo = fmaf(sw[rr + e + 201], v1, bo);
                    }
                }
            }
        }
        #pragma unroll
        for (int d = 1; d <= 2; d <<= 1) {
            xe += __shfl_xor_sync(0xffffffffu, xe, d);
            xo += __shfl_xor_sync(0xffffffffu, xo, d);
            ae += __shfl_xor_sync(0xffffffffu, ae, d);
            ao += __shfl_xor_sync(0xffffffffu, ao, d);
            be += __shfl_xor_sync(0xffffffffu, be, d);
            bo += __shfl_xor_sync(0xffffffffu, bo, d);
        }
        if (j == 0) {
            sXAB[grp][0] = xe; sXAB[grp][1] = xo;
            sXAB[grp][2] = ae; sXAB[grp][3] = ao;
            sXAB[grp][4] = be; sXAB[grp][5] = bo;
        }
        __syncthreads();

        if (tid < 2 * AOUT) {
            const int ql = tid >> 1, par = tid & 1;
            const int q  = Q0 + ql;
            if (q < NHOP) {
                float s[4];
                #pragma unroll
                for (int jj = 0; jj < 4; jj++) {
                    const int f  = q - jj;
                    const int fl = ql + 3 - jj;
                    const float v = sXAB[fl][2 + par] + sXAB[fl + 1][4 + par]
                                  + (sXAB[fl + 2][par] - sXAB[fl + 2][2 + par])
                                  + (sXAB[fl + 3][par] - sXAB[fl + 3][4 + par]);
                    s[jj] = (f < 0 || f >= N_FRAMES) ? 0.0f : v;
                }
                float* __restrict__ cp = gC[b][q];
                cp[0 + par] = s[2] + s[3];
                cp[2 + par] = s[0] - s[2];
                cp[4 + par] = s[1] - s[3];
            }
        }
        __syncthreads();
        if (tid == 0) {
            __threadfence();                      // publish gC[b] writes
            atomicAdd(&gDone[b], 1u);
        }
    } else {
        // ---------------- consumer (B): streaming synthesis ----------------
        float* __restrict__ sw = sbuf;            // win[0..800)
        for (int i = tid; i < N_FFT; i += 256)
            sw[i] = 0.5f - 0.5f * __cosf((float)i * (float)(2.0 * PI_D / N_FFT));
        __syncthreads();

        // Wait until all 42 producer blocks of this batch have signaled.
        if (tid == 0) {
            while (*((volatile unsigned int*)&gDone[b]) < (unsigned)ATILES)
                __nanosleep(128);
        }
        __syncthreads();
        __threadfence();                          // order gC reads after spin

        const int bx = r - ATILES;                // 0..36
        const float4* __restrict__ sw4 = (const float4*)sw;
        const float4* __restrict__ x4  = (const float4*)(x + (size_t)b * TLEN);
        float4* __restrict__ o4        = (float4*)(out + (size_t)b * TLEN);
        const float* __restrict__ cbase = &gC[b][0][0];

        #pragma unroll 2
        for (int v = bx * 256 + tid; v < NQUAD; v += BBLK * 256) {
            const int u  = v + 100;               // (4v + PAD)/4
            const int q  = u / 50;                // frame position
            const int r4 = u - 50 * q;            // r = 4*r4
            const float4 xv = __ldg(&x4[v]);
            const float4 w0 = sw4[r4];
            const float4 w1 = sw4[r4 + 50];
            const float* __restrict__ cp = cbase + 8 * q;
            const float4 cA = *(const float4*)cp;        // C0e,C0o,C1e,C1o
            const float4 cB = *(const float4*)(cp + 4);  // C2e,C2o,0,0
            float4 o;   // parities: x,z even; y,w odd
            o.x = fmaf(0.75f, xv.x, fmaf(w1.x, cB.x, fmaf(w0.x, cA.z, cA.x)) * (1.0f / 800.0f));
            o.y = fmaf(0.75f, xv.y, fmaf(w1.y, cB.y, fmaf(w0.y, cA.w, cA.y)) * (1.0f / 800.0f));
            o.z = fmaf(0.75f, xv.z, fmaf(w1.z, cB.x, fmaf(w0.z, cA.z, cA.x)) * (1.0f / 800.0f));
            o.w = fmaf(0.75f, xv.w, fmaf(w1.w, cB.y, fmaf(w0.w, cA.w, cA.y)) * (1.0f / 800.0f));
            if (v < 50) {                         // missing frame j=3 (win r+600)
                const float4 w3 = sw4[r4 + 150];
                o.x = fmaf(-0.5f * w3.x * w3.x, xv.x, o.x);
                o.y = fmaf(-0.5f * w3.y * w3.y, xv.y, o.y);
                o.z = fmaf(-0.5f * w3.z * w3.z, xv.z, o.z);
                o.w = fmaf(-0.5f * w3.w * w3.w, xv.w, o.w);
            }
            if (v >= NQUAD - 50) {                // missing frame j=0 (win r)
                o.x = fmaf(-0.5f * w0.x * w0.x, xv.x, o.x);
                o.y = fmaf(-0.5f * w0.y * w0.y, xv.y, o.y);
                o.z = fmaf(-0.5f * w0.z * w0.z, xv.z, o.z);
                o.w = fmaf(-0.5f * w0.w * w0.w, xv.w, o.w);
            }
            __stcs(&o4[v], o);                    // streaming store (write-once)
        }
    }
}

extern "C" void kernel_launch(void* const* d_in, const int* in_sizes, int n_in,
                              void* d_out, int out_size) {
    const float* x = (const float*)d_in[0];
    float* out = (float*)d_out;

    reset_kernel<<<1, 32>>>();
    fused_kernel<<<BATCH * RPB, 256>>>(x, out);   // 2528 blocks, batch-interleaved
}

// round 16
// speedup vs baseline: 1.2433x; 1.2433x over previous
#include <cuda_runtime.h>

#define N_FFT    800
#define HOP      200
#define BATCH    32
#define TLEN     480000
#define PAD      400
#define N_FRAMES 2401                 // frames per batch
#define NHOP     2404                 // hop blocks per batch: 480800/200
#define AOUT     58                   // C outputs (q positions) per A-block
#define AHOPS    64                   // hop sums per block incl. 3+3 halo
#define NQUAD    (TLEN / 4)           // 120000 output quads per batch
#define BGRID    37                   // B: x-grid; 37*32 = 1184 = 148 SMs * 8

#define PI_D 3.14159265358979323846

// Fully fused STFT->mag/phase->iSTFT (linear-collapse derivation, R3/R6):
//   Hann identities: win(r+400)=1-win(r), win(r+600)=1-win(r+200),
//   sum_j win(r+200j)^2 = 1.5 exactly.
//   Per hop block g: X=sum(x), A=sum(win(r)x), B=sum(win(r+200)x) (per parity).
//   S[f] = A[f] + B[f+1] + (X[f+2]-A[f+2]) + (X[f+3]-B[f+3]);  S=0 off-range.
//   out = 0.75*x + (C0 + win(r)*C1 + win(r+200)*C2)/800,
//     C0=S[q-2]+S[q-3], C1=S[q]-S[q-2], C2=S[q-1]-S[q-3]  (per parity).
//   Missing frame j at signal edge additionally: out -= 0.5*x*win(r+200j)^2.
//
// R15: B computes the window quads with __sincosf + constant-angle rotation
// instead of LDS table reads (L1-wavefront diet: 18 -> 10 wf per warp-iter).

__device__ float gC[BATCH][NHOP][8];   // {C0e,C0o,C1e,C1o,C2e,C2o,0,0}

// ---------------- Kernel A: hop sums + C combos (R13, unchanged) ----------
__global__ __launch_bounds__(256, 8)
void sums_kernel(const float* __restrict__ x) {
    __shared__ __align__(16) float sw[400];       // win[0..400)
    __shared__ float sXAB[AHOPS][6];              // {Xe,Xo,Ae,Ao,Be,Bo}

    const int b   = blockIdx.y;
    const int Q0  = blockIdx.x * AOUT;
    const int tid = threadIdx.x;
    const float* __restrict__ xb = x + (size_t)b * TLEN;

    for (int i = tid; i < 400; i += 256)
        sw[i] = 0.5f - 0.5f * __cosf((float)i * (float)(2.0 * PI_D / N_FFT));
    __syncthreads();

    const int grp = tid >> 2;                     // 0..63
    const int j   = tid & 3;
    const int gh  = Q0 - 3 + grp;                 // hop index (may be off-range)
    const float4* __restrict__ sw4 = (const float4*)sw;

    float xe = 0.f, xo = 0.f, ae = 0.f, ao = 0.f, be = 0.f, bo = 0.f;
    if (gh >= 2 && gh <= 2401) {
        const float4* __restrict__ xs = (const float4*)xb + (50 * gh - 100);
        #pragma unroll
        for (int k = 0; k < 13; k++) {
            const int c = j + 4 * k;
            if (c < 50) {
                const float4 v  = __ldg(&xs[c]);
                const float4 wa = sw4[c];
                const float4 wb = sw4[c + 50];
                xe += v.x + v.z;                   xo += v.y + v.w;
                ae = fmaf(wa.x, v.x, fmaf(wa.z, v.z, ae));
                ao = fmaf(wa.y, v.y, fmaf(wa.w, v.w, ao));
                be = fmaf(wb.x, v.x, fmaf(wb.z, v.z, be));
                bo = fmaf(wb.y, v.y, fmaf(wb.w, v.w, bo));
            }
        }
    } else {
        #pragma unroll
        for (int k = 0; k < 13; k++) {
            const int c = j + 4 * k;
            if (c < 50) {
                const int r = 4 * c;
                #pragma unroll
                for (int e = 0; e < 4; e += 2) {
                    int p0 = 200 * gh + r + e - PAD;
                    int p1 = p0 + 1;
                    p0 = p0 < 0 ? 0 : (p0 >= TLEN ? TLEN - 1 : p0);
                    p1 = p1 < 0 ? 0 : (p1 >= TLEN ? TLEN - 1 : p1);
                    const float v0 = xb[p0], v1 = xb[p1];
                    xe += v0;                         xo += v1;
                    ae = fmaf(sw[r + e], v0, ae);     ao = fmaf(sw[r + e + 1], v1, ao);
                    be = fmaf(sw[r + e + 200], v0, be);
                    bo = fmaf(sw[r + e + 201], v1, bo);
                }
            }
        }
    }
    #pragma unroll
    for (int d = 1; d <= 2; d <<= 1) {
        xe += __shfl_xor_sync(0xffffffffu, xe, d);
        xo += __shfl_xor_sync(0xffffffffu, xo, d);
        ae += __shfl_xor_sync(0xffffffffu, ae, d);
        ao += __shfl_xor_sync(0xffffffffu, ao, d);
        be += __shfl_xor_sync(0xffffffffu, be, d);
        bo += __shfl_xor_sync(0xffffffffu, bo, d);
    }
    if (j == 0) {
        sXAB[grp][0] = xe; sXAB[grp][1] = xo;
        sXAB[grp][2] = ae; sXAB[grp][3] = ao;
        sXAB[grp][4] = be; sXAB[grp][5] = bo;
    }
    __syncthreads();

    if (tid < 2 * AOUT) {
        const int ql = tid >> 1, par = tid & 1;   // ql in [0,58)
        const int q  = Q0 + ql;
        if (q < NHOP) {
            float s[4];                           // s[jj] = S(q - jj)
            #pragma unroll
            for (int jj = 0; jj < 4; jj++) {
                const int f  = q - jj;
                const int fl = ql + 3 - jj;       // 0..60; fl+3 <= 63
                const float v = sXAB[fl][2 + par] + sXAB[fl + 1][4 + par]
                              + (sXAB[fl + 2][par] - sXAB[fl + 2][2 + par])
                              + (sXAB[fl + 3][par] - sXAB[fl + 3][4 + par]);
                s[jj] = (f < 0 || f >= N_FRAMES) ? 0.0f : v;
            }
            float* __restrict__ cp = gC[b][q];
            cp[0 + par] = s[2] + s[3];            // C0
            cp[2 + par] = s[0] - s[2];            // C1
            cp[4 + par] = s[1] - s[3];            // C2
        }
    }
}

// ---------------- Kernel B: streaming synthesis, computed window ----------
// Single wave (1184 blocks @ occ 8); window via __sincosf + rotation, no smem.
// Rotation constants: delta = pi/400; (Ck, Sk) = (cos k*delta, sin k*delta).
#define ROT_C1 0.99996915760f
#define ROT_S1 0.00785390090f
#define ROT_C2 0.99987663248f
#define ROT_S2 0.01570731731f
#define ROT_C3 0.99972242766f
#define ROT_S3 0.02355976480f

__global__ __launch_bounds__(256, 8)
void synth_kernel(const float* __restrict__ x, float* __restrict__ out) {
    const int b   = blockIdx.y;
    const int tid = threadIdx.x;

    const float4* __restrict__ x4  = (const float4*)(x + (size_t)b * TLEN);
    float4* __restrict__ o4        = (float4*)(out + (size_t)b * TLEN);
    const float* __restrict__ cbase = &gC[b][0][0];

    #pragma unroll 2
    for (int v = blockIdx.x * 256 + tid; v < NQUAD; v += BGRID * 256) {
        const int u  = v + 100;                   // (4v + PAD)/4
        const int q  = u / 50;                    // frame position
        const int r4 = u - 50 * q;                // r = 4*r4, theta = pi*r/400
        float s0, c0;
        __sincosf((float)r4 * (float)(PI_D / 100.0), &s0, &c0);
        const float c1 = fmaf(c0, ROT_C1, -s0 * ROT_S1);
        const float s1 = fmaf(s0, ROT_C1,  c0 * ROT_S1);
        const float c2 = fmaf(c0, ROT_C2, -s0 * ROT_S2);
        const float s2 = fmaf(s0, ROT_C2,  c0 * ROT_S2);
        const float c3 = fmaf(c0, ROT_C3, -s0 * ROT_S3);
        const float s3 = fmaf(s0, ROT_C3,  c0 * ROT_S3);
        float4 w0, w1;                            // win(r+k), win(r+200+k)
        w0.x = fmaf(-0.5f, c0, 0.5f);  w1.x = fmaf(0.5f, s0, 0.5f);
        w0.y = fmaf(-0.5f, c1, 0.5f);  w1.y = fmaf(0.5f, s1, 0.5f);
        w0.z = fmaf(-0.5f, c2, 0.5f);  w1.z = fmaf(0.5f, s2, 0.5f);
        w0.w = fmaf(-0.5f, c3, 0.5f);  w1.w = fmaf(0.5f, s3, 0.5f);

        const float4 xv = __ldg(&x4[v]);
        const float* __restrict__ cp = cbase + 8 * q;
        const float4 cA = *(const float4*)cp;          // C0e,C0o,C1e,C1o
        const float2 cB = *(const float2*)(cp + 4);    // C2e,C2o
        float4 o;   // parities: x,z even; y,w odd
        o.x = fmaf(0.75f, xv.x, fmaf(w1.x, cB.x, fmaf(w0.x, cA.z, cA.x)) * (1.0f / 800.0f));
        o.y = fmaf(0.75f, xv.y, fmaf(w1.y, cB.y, fmaf(w0.y, cA.w, cA.y)) * (1.0f / 800.0f));
        o.z = fmaf(0.75f, xv.z, fmaf(w1.z, cB.x, fmaf(w0.z, cA.z, cA.x)) * (1.0f / 800.0f));
        o.w = fmaf(0.75f, xv.w, fmaf(w1.w, cB.y, fmaf(w0.w, cA.w, cA.y)) * (1.0f / 800.0f));
        // Edge wsq corrections (first/last 50 quads of each batch only).
        if (v < 50) {             // missing frame j=3: win(r+600) = 1 - win(r+200)
            const float4 w3 = make_float4(1.f - w1.x, 1.f - w1.y, 1.f - w1.z, 1.f - w1.w);
            o.x = fmaf(-0.5f * w3.x * w3.x, xv.x, o.x);
            o.y = fmaf(-0.5f * w3.y * w3.y, xv.y, o.y);
            o.z = fmaf(-0.5f * w3.z * w3.z, xv.z, o.z);
            o.w = fmaf(-0.5f * w3.w * w3.w, xv.w, o.w);
        }
        if (v >= NQUAD - 50) {    // missing frame j=0 (window win(r))
            o.x = fmaf(-0.5f * w0.x * w0.x, xv.x, o.x);
            o.y = fmaf(-0.5f * w0.y * w0.y, xv.y, o.y);
            o.z = fmaf(-0.5f * w0.z * w0.z, xv.z, o.z);
            o.w = fmaf(-0.5f * w0.w * w0.w, xv.w, o.w);
        }
        __stcs(&o4[v], o);                        // streaming store (write-once)
    }
}

extern "C" void kernel_launch(void* const* d_in, const int* in_sizes, int n_in,
                              void* d_out, int out_size) {
    const float* x = (const float*)d_in[0];
    float* out = (float*)d_out;

    dim3 gridA((NHOP + AOUT - 1) / AOUT, BATCH);      // 42 x 32 = 1344 blocks
    sums_kernel<<<gridA, 256>>>(x);

    dim3 gridB(BGRID, BATCH);                         // 37 x 32 = 1184 blocks
    synth_kernel<<<gridB, 256>>>(x, out);
}